// round 5
// baseline (speedup 1.0000x reference)
#include <cuda_runtime.h>

// LSTM: B=4096, T=512, I=10, H=32, O=1. Gate order i,f,g,o.
// R5: R2 layout (NB=4 batches/warp, all recurrent weights in registers as
// f32x2 j-pairs; even/odd-j halves accumulate in u64 halves) + software
// pipelining: step t+1's input-GEMV is computed into the (re-initialized)
// accumulators during step t's activation MUFU shadow. Double-buffered sX,
// bias folded into accumulator init. ONE wave: 1024 blocks, 7/SM bound.

#define B_TOT 4096
#define T_LEN 512
#define I_DIM 10
#define H_DIM 32
#define NB 4
#define NPX 5

typedef unsigned long long u64;

__device__ __forceinline__ u64 fma2(u64 a, u64 b, u64 c) {
    u64 d;
    asm("fma.rn.f32x2 %0, %1, %2, %3;" : "=l"(d) : "l"(a), "l"(b), "l"(c));
    return d;
}
__device__ __forceinline__ u64 pack2(float lo, float hi) {
    u64 d;
    asm("mov.b64 %0, {%1, %2};" : "=l"(d) : "f"(lo), "f"(hi));
    return d;
}
__device__ __forceinline__ void unpack2(u64 v, float& lo, float& hi) {
    asm("mov.b64 {%0, %1}, %2;" : "=f"(lo), "=f"(hi) : "l"(v));
}
__device__ __forceinline__ float ex2f(float x) {
    float y; asm("ex2.approx.f32 %0, %1;" : "=f"(y) : "f"(x)); return y;
}
__device__ __forceinline__ float rcpf(float x) {
    float y; asm("rcp.approx.f32 %0, %1;" : "=f"(y) : "f"(x)); return y;
}
__device__ __forceinline__ float sigf(float x) {
    return rcpf(1.0f + ex2f(-1.4426950408889634f * x));
}
__device__ __forceinline__ float tanh_f(float x) {
    return fmaf(2.0f, rcpf(1.0f + ex2f(-2.8853900817779268f * x)), -1.0f);
}

__global__ __launch_bounds__(32, 7) void lstm_pipe_kernel(
    const float* __restrict__ x,    // [B, T, I]
    const float* __restrict__ Wih,  // [4H, I]
    const float* __restrict__ Whh,  // [4H, H]
    const float* __restrict__ bih,  // [4H]
    const float* __restrict__ bhh,  // [4H]
    const float* __restrict__ Wd,   // [1, H]
    const float* __restrict__ bd,   // [1]
    float* __restrict__ out)        // [B, 1]
{
    __shared__ ulonglong2 sWx_if[NPX][32];
    __shared__ ulonglong2 sWx_go[NPX][32];
    __shared__ __align__(16) float sH[NB][H_DIM];
    __shared__ __align__(16) float sX[2][NB][12];   // double-buffered, 48B rows

    const int lane = threadIdx.x;
    const int b0 = blockIdx.x * NB;

    // ---- Recurrent weights into registers (paired over j) ----
    u64 whi[16], whf[16], whg[16], who[16];
#pragma unroll
    for (int p = 0; p < 16; p++) {
        whi[p] = *(const u64*)&Whh[(0 * 32 + lane) * H_DIM + 2 * p];
        whf[p] = *(const u64*)&Whh[(1 * 32 + lane) * H_DIM + 2 * p];
        whg[p] = *(const u64*)&Whh[(2 * 32 + lane) * H_DIM + 2 * p];
        who[p] = *(const u64*)&Whh[(3 * 32 + lane) * H_DIM + 2 * p];
    }
    // x-weights into smem, packed per gate-pair.
#pragma unroll
    for (int p = 0; p < NPX; p++) {
        ulonglong2 v;
        v.x = pack2(Wih[(0 * 32 + lane) * I_DIM + 2 * p], Wih[(0 * 32 + lane) * I_DIM + 2 * p + 1]);
        v.y = pack2(Wih[(1 * 32 + lane) * I_DIM + 2 * p], Wih[(1 * 32 + lane) * I_DIM + 2 * p + 1]);
        sWx_if[p][lane] = v;
        v.x = pack2(Wih[(2 * 32 + lane) * I_DIM + 2 * p], Wih[(2 * 32 + lane) * I_DIM + 2 * p + 1]);
        v.y = pack2(Wih[(3 * 32 + lane) * I_DIM + 2 * p], Wih[(3 * 32 + lane) * I_DIM + 2 * p + 1]);
        sWx_go[p][lane] = v;
    }
    // Bias packed into accumulator init: (bias, 0); final preact = lo + hi.
    const u64 bp_i = pack2(bih[0 * 32 + lane] + bhh[0 * 32 + lane], 0.0f);
    const u64 bp_f = pack2(bih[1 * 32 + lane] + bhh[1 * 32 + lane], 0.0f);
    const u64 bp_g = pack2(bih[2 * 32 + lane] + bhh[2 * 32 + lane], 0.0f);
    const u64 bp_o = pack2(bih[3 * 32 + lane] + bhh[3 * 32 + lane], 0.0f);

    // ---- State + x prefetch pipeline ----
    float h[NB], c[NB], xv[NB];
    const float* xp[NB];
#pragma unroll
    for (int k = 0; k < NB; k++) {
        h[k] = 0.0f; c[k] = 0.0f; xv[k] = 0.0f;
        sH[k][lane] = 0.0f;
        xp[k] = x + ((b0 + k) * T_LEN) * I_DIM + lane;
    }
    if (lane < I_DIM) {
#pragma unroll
        for (int k = 0; k < NB; k++) {
            sX[0][k][lane] = xp[k][0];          // x[0]
            sX[1][k][lane] = xp[k][I_DIM];      // x[1]
            xv[k]          = xp[k][2 * I_DIM];  // x[2]
            xp[k] += 3 * I_DIM;                 // next LDG -> x[3]
        }
    }
    __syncwarp();

    // acc = bias + x-part(t=0)
    u64 ai[NB], af[NB], ag[NB], ao[NB];
#pragma unroll
    for (int k = 0; k < NB; k++) { ai[k] = bp_i; af[k] = bp_f; ag[k] = bp_g; ao[k] = bp_o; }
#pragma unroll
    for (int p = 0; p < NPX; p++) {
        const ulonglong2 wif = sWx_if[p][lane];
        const ulonglong2 wgo = sWx_go[p][lane];
#pragma unroll
        for (int k = 0; k < NB; k++) {
            const u64 xq = *(const u64*)&sX[0][k][2 * p];
            ai[k] = fma2(wif.x, xq, ai[k]);
            af[k] = fma2(wif.y, xq, af[k]);
            ag[k] = fma2(wgo.x, xq, ag[k]);
            ao[k] = fma2(wgo.y, xq, ao[k]);
        }
    }

    for (int t = 0; t < T_LEN; t++) {
        // ---- Recurrent part: acc += Whh · h[t] ----
#pragma unroll
        for (int k = 0; k < NB; k++) {
#pragma unroll
            for (int q = 0; q < 8; q++) {
                const ulonglong2 hp = *(const ulonglong2*)&sH[k][4 * q];
                ai[k] = fma2(whi[2 * q],     hp.x, ai[k]);
                af[k] = fma2(whf[2 * q],     hp.x, af[k]);
                ag[k] = fma2(whg[2 * q],     hp.x, ag[k]);
                ao[k] = fma2(who[2 * q],     hp.x, ao[k]);
                ai[k] = fma2(whi[2 * q + 1], hp.y, ai[k]);
                af[k] = fma2(whf[2 * q + 1], hp.y, af[k]);
                ag[k] = fma2(whg[2 * q + 1], hp.y, ag[k]);
                ao[k] = fma2(who[2 * q + 1], hp.y, ao[k]);
            }
        }

        // ---- Unpack preacts; re-init accumulators with bias ----
        float pi[NB], pf[NB], pg[NB], po[NB];
#pragma unroll
        for (int k = 0; k < NB; k++) {
            float lo, hi;
            unpack2(ai[k], lo, hi); pi[k] = lo + hi; ai[k] = bp_i;
            unpack2(af[k], lo, hi); pf[k] = lo + hi; af[k] = bp_f;
            unpack2(ag[k], lo, hi); pg[k] = lo + hi; ag[k] = bp_g;
            unpack2(ao[k], lo, hi); po[k] = lo + hi; ao[k] = bp_o;
        }

        // ---- x-part for step t+1 (fills the activation MUFU shadow) ----
        const int rb = (t + 1) & 1;   // buffer holding x[t+1]
#pragma unroll
        for (int p = 0; p < NPX; p++) {
            const ulonglong2 wif = sWx_if[p][lane];
            const ulonglong2 wgo = sWx_go[p][lane];
#pragma unroll
            for (int k = 0; k < NB; k++) {
                const u64 xq = *(const u64*)&sX[rb][k][2 * p];
                ai[k] = fma2(wif.x, xq, ai[k]);
                af[k] = fma2(wif.y, xq, af[k]);
                ag[k] = fma2(wgo.x, xq, ag[k]);
                ao[k] = fma2(wgo.y, xq, ao[k]);
            }
        }
        __syncwarp();   // all lanes done reading sH / sX before overwrites below

        // ---- Activations + state update (MUFU chains) ----
#pragma unroll
        for (int k = 0; k < NB; k++) {
            const float gi = sigf(pi[k]);
            const float gf = sigf(pf[k]);
            const float gg = tanh_f(pg[k]);
            const float go = sigf(po[k]);
            c[k] = fmaf(gf, c[k], gi * gg);
            h[k] = go * tanh_f(c[k]);
        }

        // ---- Publish h[t+1]; rotate x pipeline (store x[t+2], LDG x[t+3]) ----
#pragma unroll
        for (int k = 0; k < NB; k++)
            sH[k][lane] = h[k];
        if (lane < I_DIM) {
            const int wbuf = t & 1;
#pragma unroll
            for (int k = 0; k < NB; k++) {
                sX[wbuf][k][lane] = xv[k];
                xv[k] = *xp[k];
                if (t + 4 < T_LEN) xp[k] += I_DIM;   // clamp at x[T-1]
            }
        }
        __syncwarp();
    }

    // ---- Final dense: out[b] = sum_l h[b][l] * Wd[l] + bd ----
    const float wd = Wd[lane];
    const float bdv = bd[0];
#pragma unroll
    for (int k = 0; k < NB; k++) {
        float p = h[k] * wd;
#pragma unroll
        for (int off = 16; off; off >>= 1)
            p += __shfl_xor_sync(0xffffffffu, p, off);
        if (lane == 0) out[b0 + k] = p + bdv;
    }
}

extern "C" void kernel_launch(void* const* d_in, const int* in_sizes, int n_in,
                              void* d_out, int out_size) {
    const float* x   = (const float*)d_in[0];
    const float* Wih = (const float*)d_in[1];
    const float* Whh = (const float*)d_in[2];
    const float* bih = (const float*)d_in[3];
    const float* bhh = (const float*)d_in[4];
    const float* Wd  = (const float*)d_in[5];
    const float* bd  = (const float*)d_in[6];
    (void)in_sizes; (void)n_in; (void)out_size;

    lstm_pipe_kernel<<<B_TOT / NB, 32>>>(x, Wih, Whh, bih, bhh, Wd, bd,
                                         (float*)d_out);
}

// round 6
// speedup vs baseline: 1.5605x; 1.5605x over previous
#include <cuda_runtime.h>

// LSTM: B=4096, T=512, I=10, H=32, O=1. Gate order i,f,g,o.
// R6: NB=4 batches/warp, ALL weights (recurrent + input) in registers as
// f32x2 pairs; even/odd-index halves accumulate in the u64 halves.
// Cross-batch software pipelining: per batch k do {recurrent, x-part,
// activations, publish h}, so batch k+1's fma stream hides batch k's MUFU
// chain. sH/sX are ping-pong buffered with COMPILE-TIME parity (t-loop
// unrolled x2) -> all smem addresses static. One __syncwarp per step.
// One wave: 1024 single-warp blocks, 7 blocks/SM bound.

#define B_TOT 4096
#define T_LEN 512
#define I_DIM 10
#define H_DIM 32
#define NB 4

typedef unsigned long long u64;

__device__ __forceinline__ u64 fma2(u64 a, u64 b, u64 c) {
    u64 d;
    asm("fma.rn.f32x2 %0, %1, %2, %3;" : "=l"(d) : "l"(a), "l"(b), "l"(c));
    return d;
}
__device__ __forceinline__ u64 pack2(float lo, float hi) {
    u64 d;
    asm("mov.b64 %0, {%1, %2};" : "=l"(d) : "f"(lo), "f"(hi));
    return d;
}
__device__ __forceinline__ void unpack2(u64 v, float& lo, float& hi) {
    asm("mov.b64 {%0, %1}, %2;" : "=f"(lo), "=f"(hi) : "l"(v));
}
__device__ __forceinline__ float ex2f(float x) {
    float y; asm("ex2.approx.f32 %0, %1;" : "=f"(y) : "f"(x)); return y;
}
__device__ __forceinline__ float rcpf(float x) {
    float y; asm("rcp.approx.f32 %0, %1;" : "=f"(y) : "f"(x)); return y;
}
__device__ __forceinline__ float sigf(float x) {
    return rcpf(1.0f + ex2f(-1.4426950408889634f * x));
}
__device__ __forceinline__ float tanh_f(float x) {
    return fmaf(2.0f, rcpf(1.0f + ex2f(-2.8853900817779268f * x)), -1.0f);
}

struct Wregs {
    u64 whi[16], whf[16], whg[16], who[16];   // recurrent j-pairs
    u64 wxi[5],  wxf[5],  wxg[5],  wxo[5];    // input i-pairs
    u64 bp_i, bp_f, bp_g, bp_o;               // (bias, 0)
};

// One timestep. A = read-buffer parity (compile-time), writes buffer A^1.
template<int A>
__device__ __forceinline__ void lstm_step(
    int lane, int t, const Wregs& W,
    float (&h)[NB], float (&c)[NB], float (&xv)[NB],
    float (*sH)[NB][H_DIM], float (*sX)[NB][12],
    const float* __restrict__ xbase)
{
    constexpr int Bw = A ^ 1;
#pragma unroll
    for (int k = 0; k < NB; k++) {
        u64 ai = W.bp_i, af = W.bp_f, ag = W.bp_g, ao = W.bp_o;
        // Recurrent: 8 x 16B broadcast chunks of h (16 j-pairs).
#pragma unroll
        for (int q = 0; q < 8; q++) {
            const ulonglong2 hp = *(const ulonglong2*)&sH[A][k][4 * q];
            ai = fma2(W.whi[2 * q],     hp.x, ai);
            af = fma2(W.whf[2 * q],     hp.x, af);
            ag = fma2(W.whg[2 * q],     hp.x, ag);
            ao = fma2(W.who[2 * q],     hp.x, ao);
            ai = fma2(W.whi[2 * q + 1], hp.y, ai);
            af = fma2(W.whf[2 * q + 1], hp.y, af);
            ag = fma2(W.whg[2 * q + 1], hp.y, ag);
            ao = fma2(W.who[2 * q + 1], hp.y, ao);
        }
        // Input part: 5 x-pairs, weights in registers.
#pragma unroll
        for (int p = 0; p < 5; p++) {
            const u64 xq = *(const u64*)&sX[A][k][2 * p];
            ai = fma2(W.wxi[p], xq, ai);
            af = fma2(W.wxf[p], xq, af);
            ag = fma2(W.wxg[p], xq, ag);
            ao = fma2(W.wxo[p], xq, ao);
        }
        // Activations for batch k (MUFU chain overlapped by batch k+1's fma).
        float lo, hi;
        unpack2(ai, lo, hi); const float gi = sigf(lo + hi);
        unpack2(af, lo, hi); const float gf = sigf(lo + hi);
        unpack2(ag, lo, hi); const float gg = tanh_f(lo + hi);
        unpack2(ao, lo, hi); const float go = sigf(lo + hi);
        c[k] = fmaf(gf, c[k], gi * gg);
        h[k] = go * tanh_f(c[k]);
        sH[Bw][k][lane] = h[k];
    }
    // Rotate x pipeline: publish x[t+1], LDG x[t+2] (clamped).
    if (lane < I_DIM) {
        const int off = (t + 2 < T_LEN) ? (t + 2) * I_DIM : (T_LEN - 1) * I_DIM;
#pragma unroll
        for (int k = 0; k < NB; k++) {
            sX[Bw][k][lane] = xv[k];
            xv[k] = xbase[k * T_LEN * I_DIM + off];
        }
    }
    __syncwarp();
}

__global__ __launch_bounds__(32, 7) void lstm_r6_kernel(
    const float* __restrict__ x,    // [B, T, I]
    const float* __restrict__ Wih,  // [4H, I]
    const float* __restrict__ Whh,  // [4H, H]
    const float* __restrict__ bih,  // [4H]
    const float* __restrict__ bhh,  // [4H]
    const float* __restrict__ Wd,   // [1, H]
    const float* __restrict__ bd,   // [1]
    float* __restrict__ out)        // [B, 1]
{
    __shared__ __align__(16) float sH[2][NB][H_DIM];   // 1 KB ping-pong
    __shared__ __align__(16) float sX[2][NB][12];      // 384 B ping-pong

    const int lane = threadIdx.x;
    const int b0 = blockIdx.x * NB;

    Wregs W;
#pragma unroll
    for (int p = 0; p < 16; p++) {
        W.whi[p] = *(const u64*)&Whh[(0 * 32 + lane) * H_DIM + 2 * p];
        W.whf[p] = *(const u64*)&Whh[(1 * 32 + lane) * H_DIM + 2 * p];
        W.whg[p] = *(const u64*)&Whh[(2 * 32 + lane) * H_DIM + 2 * p];
        W.who[p] = *(const u64*)&Whh[(3 * 32 + lane) * H_DIM + 2 * p];
    }
#pragma unroll
    for (int p = 0; p < 5; p++) {
        W.wxi[p] = *(const u64*)&Wih[(0 * 32 + lane) * I_DIM + 2 * p];
        W.wxf[p] = *(const u64*)&Wih[(1 * 32 + lane) * I_DIM + 2 * p];
        W.wxg[p] = *(const u64*)&Wih[(2 * 32 + lane) * I_DIM + 2 * p];
        W.wxo[p] = *(const u64*)&Wih[(3 * 32 + lane) * I_DIM + 2 * p];
    }
    W.bp_i = pack2(bih[0 * 32 + lane] + bhh[0 * 32 + lane], 0.0f);
    W.bp_f = pack2(bih[1 * 32 + lane] + bhh[1 * 32 + lane], 0.0f);
    W.bp_g = pack2(bih[2 * 32 + lane] + bhh[2 * 32 + lane], 0.0f);
    W.bp_o = pack2(bih[3 * 32 + lane] + bhh[3 * 32 + lane], 0.0f);

    float h[NB], c[NB], xv[NB];
    const float* xbase = x + b0 * T_LEN * I_DIM + lane;
#pragma unroll
    for (int k = 0; k < NB; k++) {
        h[k] = 0.0f; c[k] = 0.0f; xv[k] = 0.0f;
        sH[0][k][lane] = 0.0f;
    }
    if (lane < I_DIM) {
#pragma unroll
        for (int k = 0; k < NB; k++) {
            sX[0][k][lane] = xbase[k * T_LEN * I_DIM];          // x[0]
            xv[k]          = xbase[k * T_LEN * I_DIM + I_DIM];  // x[1]
        }
    }
    __syncwarp();

#pragma unroll 1
    for (int t = 0; t < T_LEN; t += 2) {
        lstm_step<0>(lane, t,     W, h, c, xv, sH, sX, xbase);
        lstm_step<1>(lane, t + 1, W, h, c, xv, sH, sX, xbase);
    }

    // Final dense: out[b] = sum_l h[b][l] * Wd[l] + bd
    const float wd = Wd[lane];
    const float bdv = bd[0];
#pragma unroll
    for (int k = 0; k < NB; k++) {
        float p = h[k] * wd;
#pragma unroll
        for (int off = 16; off; off >>= 1)
            p += __shfl_xor_sync(0xffffffffu, p, off);
        if (lane == 0) out[b0 + k] = p + bdv;
    }
}

extern "C" void kernel_launch(void* const* d_in, const int* in_sizes, int n_in,
                              void* d_out, int out_size) {
    const float* x   = (const float*)d_in[0];
    const float* Wih = (const float*)d_in[1];
    const float* Whh = (const float*)d_in[2];
    const float* bih = (const float*)d_in[3];
    const float* bhh = (const float*)d_in[4];
    const float* Wd  = (const float*)d_in[5];
    const float* bd  = (const float*)d_in[6];
    (void)in_sizes; (void)n_in; (void)out_size;

    lstm_r6_kernel<<<B_TOT / NB, 32>>>(x, Wih, Whh, bih, bhh, Wd, bd,
                                       (float*)d_out);
}